// round 10
// baseline (speedup 1.0000x reference)
#include <cuda_runtime.h>
#include <cuda_fp16.h>
#include <math.h>

#define BB   8
#define TT   2048
#define CC   96
#define NH   3
#define HD   32
#define DFF  2048
#define HW   32
#define NKEY 65
#define EPSL 1e-5f

// ---- scratch (device globals; no allocation allowed) ----
__device__ float  g_h1 [(size_t)BB * CC * TT];      // post-LN1 (fp32, feature-major)
__device__ __half g_h16[(size_t)BB * TT * CC];      // post-LN1 (fp16, token-major)
__device__ __half g_w1h[(size_t)DFF * CC];          // fp16 W1
__device__ __half g_w2h[(size_t)CC * DFF];          // fp16 W2
__device__ __half g_wqh[(size_t)3 * CC * CC];       // fp16 W_qkv
__device__ __half g_woh[(size_t)CC * CC];           // fp16 W_out
__device__ __half g_x16[(size_t)BB * TT * CC];      // x, token-major fp16
__device__ __half g_qkv16[(size_t)BB * TT * 3 * CC];// qkv, token-major fp16

// =====================================================================
__device__ __forceinline__ void mma16(float* d, const unsigned* a, const unsigned* b) {
    asm("mma.sync.aligned.m16n8k16.row.col.f32.f16.f16.f32 "
        "{%0,%1,%2,%3}, {%4,%5,%6,%7}, {%8,%9}, {%0,%1,%2,%3};"
        : "+f"(d[0]), "+f"(d[1]), "+f"(d[2]), "+f"(d[3])
        : "r"(a[0]), "r"(a[1]), "r"(a[2]), "r"(a[3]), "r"(b[0]), "r"(b[1]));
}
__device__ __forceinline__ void cpa16(void* dst, const void* src) {
    unsigned d = (unsigned)__cvta_generic_to_shared(dst);
    asm volatile("cp.async.cg.shared.global [%0], [%1], 16;" :: "r"(d), "l"(src));
}
__device__ __forceinline__ void cpa_commit() {
    asm volatile("cp.async.commit_group;" ::: "memory");
}

// =====================================================================
// Kernel 0 (MERGED): weight prep + x transpose in one launch.
// =====================================================================
#define PREP_BLKS 768

__global__ __launch_bounds__(256) void k_prep(const float* __restrict__ w1,
                                              const float* __restrict__ w2,
                                              const float* __restrict__ wq,
                                              const float* __restrict__ wo,
                                              const float* __restrict__ x) {
    int bx = blockIdx.x;
    if (bx < PREP_BLKS) {
        int i = bx * 256 + threadIdx.x;
        if (i < DFF * CC) {
            g_w1h[i] = __float2half_rn(w1[i]);
            g_w2h[i] = __float2half_rn(w2[i]);
        }
        if (i < 3 * CC * CC) g_wqh[i] = __float2half_rn(wq[i]);
        if (i < CC * CC)     g_woh[i] = __float2half_rn(wo[i]);
        return;
    }
    __shared__ float tile[32][33];
    int bx2 = bx - PREP_BLKS;
    int tI = bx2 & 63;
    int rest = bx2 >> 6;
    int cI = rest % 3;
    int b  = rest / 3;
    int t0 = tI * 32;
    int c0 = cI * 32;
    int tx = threadIdx.x & 31, ty = threadIdx.x >> 5;

    const float* xb = x + (size_t)b * CC * TT;
#pragma unroll
    for (int i = 0; i < 4; i++)
        tile[ty + 8 * i][tx] = xb[(size_t)(c0 + ty + 8 * i) * TT + t0 + tx];
    __syncthreads();
    __half* ob = g_x16 + (size_t)b * TT * CC;
#pragma unroll
    for (int i = 0; i < 4; i++)
        ob[(size_t)(t0 + ty + 8 * i) * CC + c0 + tx] =
            __float2half_rn(tile[tx][ty + 8 * i]);
}

// =====================================================================
// Kernel 1: QKV via fp16 mma (unchanged)
// =====================================================================
#define XS2 104

__global__ __launch_bounds__(512, 1) void k_qkv(const float* __restrict__ bias) {
    extern __shared__ char smraw[];
    __half* Xs = (__half*)smraw;        // [128][104]
    __half* Wq = Xs + 128 * XS2;        // [288][104]

    int t0 = blockIdx.x * 128;
    int b  = blockIdx.y;
    int tid  = threadIdx.x;
    int lane = tid & 31;
    int w    = tid >> 5;
    int gid  = lane >> 2;
    int tig  = lane & 3;
    int m0 = (w & 3) * 32;
    int g0 = (w >> 2) * 72;

    const uint4* xsrc = (const uint4*)(g_x16 + ((size_t)b * TT + t0) * 96);
    for (int i = tid; i < 128 * 12; i += 512) {
        int tok = i / 12, seg = i - tok * 12;
        *(uint4*)(Xs + tok * XS2 + seg * 8) = xsrc[i];
    }
    const uint4* wsrc = (const uint4*)g_wqh;
    for (int i = tid; i < 288 * 12; i += 512) {
        int r = i / 12, q = i - r * 12;
        *(uint4*)(Wq + r * XS2 + q * 8) = wsrc[i];
    }
    __syncthreads();

    float acc[3][2][3][4];
#pragma unroll
    for (int jt = 0; jt < 3; jt++)
#pragma unroll
        for (int i = 0; i < 2; i++)
#pragma unroll
            for (int jj = 0; jj < 3; jj++)
#pragma unroll
                for (int r = 0; r < 4; r++) acc[jt][i][jj][r] = 0.f;

#pragma unroll
    for (int ks = 0; ks < 6; ks++) {
        int k0 = ks * 16;
        unsigned A[2][4];
#pragma unroll
        for (int i = 0; i < 2; i++) {
            const __half* base = Xs + (m0 + 16 * i + gid) * XS2 + k0 + 2 * tig;
            A[i][0] = *(const unsigned*)(base);
            A[i][1] = *(const unsigned*)(base + 8 * XS2);
            A[i][2] = *(const unsigned*)(base + 8);
            A[i][3] = *(const unsigned*)(base + 8 * XS2 + 8);
        }
#pragma unroll
        for (int jt = 0; jt < 3; jt++) {
            unsigned Bv[3][2];
#pragma unroll
            for (int jj = 0; jj < 3; jj++) {
                const __half* bb = Wq + (g0 + 24 * jt + 8 * jj + gid) * XS2 + k0 + 2 * tig;
                Bv[jj][0] = *(const unsigned*)(bb);
                Bv[jj][1] = *(const unsigned*)(bb + 8);
            }
#pragma unroll
            for (int i = 0; i < 2; i++)
#pragma unroll
                for (int jj = 0; jj < 3; jj++) mma16(acc[jt][i][jj], A[i], Bv[jj]);
        }
    }

    __half* ob = g_qkv16 + ((size_t)b * TT + t0) * 288;
#pragma unroll
    for (int jt = 0; jt < 3; jt++)
#pragma unroll
        for (int jj = 0; jj < 3; jj++) {
            int c = g0 + 24 * jt + 8 * jj + 2 * tig;
            float2 bv = *(const float2*)(bias + c);
#pragma unroll
            for (int i = 0; i < 2; i++) {
                int row = m0 + 16 * i + gid;
                __half2 lo = __floats2half2_rn(acc[jt][i][jj][0] + bv.x,
                                               acc[jt][i][jj][1] + bv.y);
                __half2 hi = __floats2half2_rn(acc[jt][i][jj][2] + bv.x,
                                               acc[jt][i][jj][3] + bv.y);
                *(__half2*)(ob + (size_t)row * 288 + c)       = lo;
                *(__half2*)(ob + (size_t)(row + 8) * 288 + c) = hi;
            }
        }
}

// =====================================================================
// Kernel 2 (FUSED): banded attention + out-proj + residual + LN1
// (unchanged)
// =====================================================================
#define QSTR 40
#define VSTR 136

__global__ __launch_bounds__(128, 1) void k_attn_oproj(const float* __restrict__ x,
                                                       const float* __restrict__ bo,
                                                       const float* __restrict__ g1,
                                                       const float* __restrict__ b1) {
    extern __shared__ char smraw[];
    __half* Qs  = (__half*)smraw;         // [64][40]
    __half* Ks  = Qs + 64 * QSTR;         // [128][40]
    __half* Vt  = Ks + 128 * QSTR;        // [32][136]
    __half* Ctx = Vt + 32 * VSTR;         // [64][104]
    __half* Wo  = Ctx + 64 * XS2;         // [96][104]
    __shared__ float BoS[96], G1S[96], B1S[96];

    int t0 = blockIdx.x * 64;
    int b  = blockIdx.y;
    int tid  = threadIdx.x;
    int lane = tid & 31;
    int w    = tid >> 5;
    int gid  = lane >> 2;
    int tig  = lane & 3;
    int m0a  = w * 16;
    int kbase = t0 - HW;

    const __half* qkvb = g_qkv16 + (size_t)b * TT * 288;

    const uint4* wsrc = (const uint4*)g_woh;
    for (int i = tid; i < 96 * 12; i += 128) {
        int r = i / 12, q = i - r * 12;
        *(uint4*)(Wo + r * XS2 + q * 8) = wsrc[i];
    }
    if (tid < 96) { BoS[tid] = bo[tid]; G1S[tid] = g1[tid]; B1S[tid] = b1[tid]; }

    for (int h = 0; h < NH; h++) {
        __syncthreads();

        for (int i = tid; i < 64 * 4; i += 128) {
            int r = i >> 2, seg = i & 3;
            *(uint4*)(Qs + r * QSTR + seg * 8) =
                *(const uint4*)(qkvb + (size_t)(t0 + r) * 288 + h * HD + seg * 8);
        }
        for (int i = tid; i < 128 * 4; i += 128) {
            int r = i >> 2, seg = i & 3;
            int s = kbase + r;
            uint4 v = make_uint4(0, 0, 0, 0);
            if (s >= 0 && s < TT)
                v = *(const uint4*)(qkvb + (size_t)s * 288 + 96 + h * HD + seg * 8);
            *(uint4*)(Ks + r * QSTR + seg * 8) = v;
        }
        {
            int r = tid;
            int s = kbase + r;
            uint4 vv[4];
            if (s >= 0 && s < TT) {
#pragma unroll
                for (int seg = 0; seg < 4; seg++)
                    vv[seg] = *(const uint4*)(qkvb + (size_t)s * 288 + 192 + h * HD + seg * 8);
            } else {
#pragma unroll
                for (int seg = 0; seg < 4; seg++) vv[seg] = make_uint4(0, 0, 0, 0);
            }
            const __half* vh = (const __half*)vv;
#pragma unroll
            for (int f = 0; f < 32; f++) Vt[f * VSTR + r] = vh[f];
        }
        __syncthreads();

        float s[16][4];
#pragma unroll
        for (int j = 0; j < 16; j++)
#pragma unroll
            for (int r = 0; r < 4; r++) s[j][r] = 0.f;

#pragma unroll
        for (int ks = 0; ks < 2; ks++) {
            int k0 = ks * 16;
            unsigned A[4];
            const __half* abase = Qs + (m0a + gid) * QSTR + k0 + 2 * tig;
            A[0] = *(const unsigned*)(abase);
            A[1] = *(const unsigned*)(abase + 8 * QSTR);
            A[2] = *(const unsigned*)(abase + 8);
            A[3] = *(const unsigned*)(abase + 8 * QSTR + 8);
#pragma unroll
            for (int j = 0; j < 16; j++) {
                unsigned Bv[2];
                const __half* bb = Ks + (8 * j + gid) * QSTR + k0 + 2 * tig;
                Bv[0] = *(const unsigned*)(bb);
                Bv[1] = *(const unsigned*)(bb + 8);
                mma16(s[j], A, Bv);
            }
        }

        const float scale = 0.17677669529663689f;
        int row0 = m0a + gid;
        int row1 = row0 + 8;
        float mx0 = -1e30f, mx1 = -1e30f;
#pragma unroll
        for (int j = 0; j < 16; j++) {
#pragma unroll
            for (int c = 0; c < 2; c++) {
                int col = 8 * j + 2 * tig + c;
                int key = kbase + col;
                bool in = (key >= 0) && (key < TT);
                bool v0 = in && (col >= row0) && (col <= row0 + 64);
                bool v1 = in && (col >= row1) && (col <= row1 + 64);
                s[j][c]     = v0 ? s[j][c] * scale     : -1e30f;
                s[j][c + 2] = v1 ? s[j][c + 2] * scale : -1e30f;
                mx0 = fmaxf(mx0, s[j][c]);
                mx1 = fmaxf(mx1, s[j][c + 2]);
            }
        }
        mx0 = fmaxf(mx0, __shfl_xor_sync(0xffffffffu, mx0, 1));
        mx0 = fmaxf(mx0, __shfl_xor_sync(0xffffffffu, mx0, 2));
        mx1 = fmaxf(mx1, __shfl_xor_sync(0xffffffffu, mx1, 1));
        mx1 = fmaxf(mx1, __shfl_xor_sync(0xffffffffu, mx1, 2));

        float sum0 = 0.f, sum1 = 0.f;
#pragma unroll
        for (int j = 0; j < 16; j++) {
            s[j][0] = __expf(s[j][0] - mx0);  sum0 += s[j][0];
            s[j][1] = __expf(s[j][1] - mx0);  sum0 += s[j][1];
            s[j][2] = __expf(s[j][2] - mx1);  sum1 += s[j][2];
            s[j][3] = __expf(s[j][3] - mx1);  sum1 += s[j][3];
        }
        sum0 += __shfl_xor_sync(0xffffffffu, sum0, 1);
        sum0 += __shfl_xor_sync(0xffffffffu, sum0, 2);
        sum1 += __shfl_xor_sync(0xffffffffu, sum1, 1);
        sum1 += __shfl_xor_sync(0xffffffffu, sum1, 2);
        float inv0 = 1.f / sum0, inv1 = 1.f / sum1;

        unsigned pa[8][4];
#pragma unroll
        for (int kt = 0; kt < 8; kt++) {
            __half2 a0 = __floats2half2_rn(s[2 * kt][0] * inv0,     s[2 * kt][1] * inv0);
            __half2 a1 = __floats2half2_rn(s[2 * kt][2] * inv1,     s[2 * kt][3] * inv1);
            __half2 a2 = __floats2half2_rn(s[2 * kt + 1][0] * inv0, s[2 * kt + 1][1] * inv0);
            __half2 a3 = __floats2half2_rn(s[2 * kt + 1][2] * inv1, s[2 * kt + 1][3] * inv1);
            pa[kt][0] = *reinterpret_cast<unsigned*>(&a0);
            pa[kt][1] = *reinterpret_cast<unsigned*>(&a1);
            pa[kt][2] = *reinterpret_cast<unsigned*>(&a2);
            pa[kt][3] = *reinterpret_cast<unsigned*>(&a3);
        }

        float o[4][4];
#pragma unroll
        for (int n = 0; n < 4; n++)
#pragma unroll
            for (int r = 0; r < 4; r++) o[n][r] = 0.f;

#pragma unroll
        for (int kt = 0; kt < 8; kt++) {
#pragma unroll
            for (int n = 0; n < 4; n++) {
                unsigned Bv[2];
                const __half* bb = Vt + (8 * n + gid) * VSTR + 16 * kt + 2 * tig;
                Bv[0] = *(const unsigned*)(bb);
                Bv[1] = *(const unsigned*)(bb + 8);
                mma16(o[n], pa[kt], Bv);
            }
        }

#pragma unroll
        for (int n = 0; n < 4; n++) {
            int col = h * HD + 8 * n + 2 * tig;
            __half2 lo = __floats2half2_rn(o[n][0], o[n][1]);
            __half2 hi = __floats2half2_rn(o[n][2], o[n][3]);
            *(__half2*)(Ctx + row0 * XS2 + col) = lo;
            *(__half2*)(Ctx + row1 * XS2 + col) = hi;
        }
    }
    __syncthreads();

    int m0 = (w & 1) * 32;
    int n0 = (w >> 1) * 48;
    float Y[2][6][4];
#pragma unroll
    for (int i = 0; i < 2; i++)
#pragma unroll
        for (int j = 0; j < 6; j++)
#pragma unroll
            for (int r = 0; r < 4; r++) Y[i][j][r] = 0.f;

#pragma unroll
    for (int ks = 0; ks < 6; ks++) {
        int k0 = ks * 16;
        unsigned A[2][4], Bv[6][2];
#pragma unroll
        for (int i = 0; i < 2; i++) {
            const __half* base = Ctx + (m0 + 16 * i + gid) * XS2 + k0 + 2 * tig;
            A[i][0] = *(const unsigned*)(base);
            A[i][1] = *(const unsigned*)(base + 8 * XS2);
            A[i][2] = *(const unsigned*)(base + 8);
            A[i][3] = *(const unsigned*)(base + 8 * XS2 + 8);
        }
#pragma unroll
        for (int j = 0; j < 6; j++) {
            const __half* bb = Wo + (n0 + 8 * j + gid) * XS2 + k0 + 2 * tig;
            Bv[j][0] = *(const unsigned*)(bb);
            Bv[j][1] = *(const unsigned*)(bb + 8);
        }
#pragma unroll
        for (int i = 0; i < 2; i++)
#pragma unroll
            for (int j = 0; j < 6; j++) mma16(Y[i][j], A[i], Bv[j]);
    }

    __syncthreads();
    float* Ys = (float*)smraw;   // [64][101]
#pragma unroll
    for (int i = 0; i < 2; i++)
#pragma unroll
        for (int j = 0; j < 6; j++) {
            int row = m0 + 16 * i + gid;
            int col = n0 + 8 * j + 2 * tig;
            Ys[row * 101 + col]           = Y[i][j][0];
            Ys[row * 101 + col + 1]       = Y[i][j][1];
            Ys[(row + 8) * 101 + col]     = Y[i][j][2];
            Ys[(row + 8) * 101 + col + 1] = Y[i][j][3];
        }
    __syncthreads();

    if (tid < 64) {
        int t = tid;
        const float* xb = x + (size_t)b * CC * TT + t0 + t;
        float* yr = Ys + t * 101;
        float mu = 0.f;
#pragma unroll
        for (int c = 0; c < 96; c++) {
            float v = yr[c] + xb[(size_t)c * TT] + BoS[c];
            yr[c] = v;
            mu += v;
        }
        mu *= (1.f / 96.f);
        float var = 0.f;
#pragma unroll
        for (int c = 0; c < 96; c++) {
            float d = yr[c] - mu;
            var += d * d;
        }
        var *= (1.f / 96.f);
        float rs = rsqrtf(var + EPSL);

        float* hb = g_h1 + (size_t)b * CC * TT + t0 + t;
        unsigned hu[48];
#pragma unroll
        for (int c = 0; c < 96; c += 2) {
            float v0 = (yr[c] - mu) * rs * G1S[c] + B1S[c];
            float v1 = (yr[c + 1] - mu) * rs * G1S[c + 1] + B1S[c + 1];
            hb[(size_t)c * TT] = v0;
            hb[(size_t)(c + 1) * TT] = v1;
            __half2 p = __floats2half2_rn(v0, v1);
            hu[c >> 1] = *reinterpret_cast<unsigned*>(&p);
        }
        uint4* dst = (uint4*)(g_h16 + ((size_t)b * TT + t0 + t) * 96);
#pragma unroll
        for (int qq = 0; qq < 12; qq++)
            dst[qq] = make_uint4(hu[4 * qq], hu[4 * qq + 1], hu[4 * qq + 2], hu[4 * qq + 3]);
    }
}

// =====================================================================
// Kernel 3: FF with warp-independent DFF slices (R9 structure, staging FIXED).
// grid (T/64, B) = 256 blocks, 256 threads (8 warps).
// Warp w: tg = w&1 (32 tokens), ds = w>>1 (512-ff slice).
// =====================================================================
#define HSF 104                     // Hs row stride (halves)
#define PBUF (16 * HSF + 96 * 16)   // per-buffer halves: W1 [16][104] + W2 [96][16]

__device__ __forceinline__ void stage_pair(int jf, __half* W1d, __half* W2d, int pl) {
    // pl = lane within warp-pair, 0..63
    // W1 slice [16 rows][96 halves] = 192 x 16B copies  (FIXED: was 96)
#pragma unroll
    for (int i = 0; i < 3; i++) {
        int idx = pl + 64 * i;              // 0..191
        int r = idx / 12, seg = idx - r * 12;
        cpa16(W1d + r * HSF + seg * 8, g_w1h + (size_t)(jf + r) * 96 + seg * 8);
    }
    // W2 slice [96 feats][16 halves] = 192 x 16B copies
#pragma unroll
    for (int i = 0; i < 3; i++) {
        int idx = pl + 64 * i;              // 0..191
        int c = idx >> 1, hf = idx & 1;
        cpa16(W2d + c * 16 + hf * 8, g_w2h + (size_t)c * DFF + jf + hf * 8);
    }
    cpa_commit();
}

__global__ __launch_bounds__(256, 1) void k_ff(const float* __restrict__ b1f,
                                               const float* __restrict__ b2f,
                                               const float* __restrict__ g2,
                                               const float* __restrict__ b2,
                                               const float* __restrict__ gf,
                                               const float* __restrict__ bf,
                                               float* __restrict__ out) {
    extern __shared__ char smraw[];
    __half* Hs = (__half*)smraw;            // [64][104]
    __half* WT = Hs + 64 * HSF;             // 4 pairs x 2 bufs x PBUF
    __shared__ float B2F[96], G2S[96], B2S[96], GFS[96], BFS[96];

    int t0 = blockIdx.x * 64;
    int b  = blockIdx.y;
    int tid  = threadIdx.x;
    int lane = tid & 31;
    int w    = tid >> 5;
    int gid  = lane >> 2;
    int tig  = lane & 3;
    int tg   = w & 1;            // token group (32 tokens)
    int ds   = w >> 1;           // DFF slice 0..3
    int pl   = tg * 32 + lane;   // lane within warp-pair
    int barid = 1 + ds;
    int m0 = tg * 32;
    int ffbase = ds * 512;

    __half* Wp = WT + ds * 2 * PBUF;

    // prefetch step 0 weights (pair-cooperative)
    stage_pair(ffbase, Wp, Wp + 16 * HSF, pl);

    // stage Hs [64][96] (block-cooperative)
    const uint4* hsrc = (const uint4*)(g_h16 + ((size_t)b * TT + t0) * 96);
    for (int i = tid; i < 64 * 12; i += 256) {
        int tok = i / 12, seg = i - tok * 12;
        *(uint4*)(Hs + tok * HSF + seg * 8) = hsrc[i];
    }
    if (tid < 96) {
        B2F[tid] = b2f[tid]; G2S[tid] = g2[tid]; B2S[tid] = b2[tid];
        GFS[tid] = gf[tid];  BFS[tid] = bf[tid];
    }
    __syncthreads();

    float Y[2][12][4];
#pragma unroll
    for (int i = 0; i < 2; i++)
#pragma unroll
        for (int n = 0; n < 12; n++)
#pragma unroll
            for (int r = 0; r < 4; r++) Y[i][n][r] = 0.f;

    for (int it = 0; it < 32; it++) {
        int jf = ffbase + it * 16;
        __half* W1c = Wp + (it & 1) * PBUF;
        __half* W2c = W1c + 16 * HSF;

        // wait own cp.async share of step it, then pair-sync
        asm volatile("cp.async.wait_group 0;" ::: "memory");
        asm volatile("bar.sync %0, 64;" :: "r"(barid) : "memory");

        // prefetch step it+1 (safe: both pair warps past iter it-1 reads)
        if (it + 1 < 32) {
            __half* W1n = Wp + ((it + 1) & 1) * PBUF;
            stage_pair(jf + 16, W1n, W1n + 16 * HSF, pl);
        }

        // ---- u = Hs(tile) @ W1ᵀ : [32 tok][16 ff] in regs ----
        float ua[2][2][4];
#pragma unroll
        for (int i = 0; i < 2; i++)
#pragma unroll
            for (int j = 0; j < 2; j++)
#pragma unroll
                for (int r = 0; r < 4; r++) ua[i][j][r] = 0.f;

#pragma unroll
        for (int ks = 0; ks < 6; ks++) {
            int k0 = ks * 16;
            unsigned A[2][4], Bv[2][2];
#pragma unroll
            for (int i = 0; i < 2; i++) {
                const __half* base = Hs + (m0 + 16 * i + gid) * HSF + k0 + 2 * tig;
                A[i][0] = *(const unsigned*)(base);
                A[i][1] = *(const unsigned*)(base + 8 * HSF);
                A[i][2] = *(const unsigned*)(base + 8);
                A[i][3] = *(const unsigned*)(base + 8 * HSF + 8);
            }
#pragma unroll
            for (int j = 0; j < 2; j++) {
                const __half* bb = W1c + (8 * j + gid) * HSF + k0 + 2 * tig;
                Bv[j][0] = *(const unsigned*)(bb);
                Bv[j][1] = *(const unsigned*)(bb + 8);
            }
#pragma unroll
            for (int i = 0; i < 2; i++)
#pragma unroll
                for (int j = 0; j < 2; j++) mma16(ua[i][j], A[i], Bv[j]);
        }

        // ---- bias + relu + in-register repack C-frag -> A-frag ----
        float2 bv0 = *(const float2*)(b1f + jf + 2 * tig);
        float2 bv1 = *(const float2*)(b1f + jf + 8 + 2 * tig);
        unsigned pa[2][4];
#pragma unroll
        for (int i = 0; i < 2; i++) {
            __half2 h0 = __floats2half2_rn(fmaxf(ua[i][0][0] + bv0.x, 0.f),
                                           fmaxf(ua[i][0][1] + bv0.y, 0.f));
            __half2 h1 = __floats2half2_rn(fmaxf(ua[i][0][2] + bv0.x, 0.f),
                                           fmaxf(ua[i][0][3] + bv0.y, 0.f));
            __half2 h2 = __floats2half2_rn(fmaxf(ua[i][1][0] + bv1.x, 0.f),
                                           fmaxf(ua[i][1][1] + bv1.y, 0.f));
            __half2 h3 = __floats2half2_rn(fmaxf(ua[i][1][2] + bv1.x, 0.f),
                                           fmaxf(ua[i][1][3] + bv1.y, 0.f));
            pa[i][0] = *reinterpret_cast<unsigned*>(&h0);
            pa[i][1] = *reinterpret_cast<unsigned*>(&h1);
            pa[i][2] = *reinterpret_cast<unsigned*>(&h2);
            pa[i][3] = *reinterpret_cast<unsigned*>(&h3);
        }

        // ---- Y += u @ W2ᵀ : k=16 (this ff step), n=96 feats ----
#pragma unroll
        for (int n = 0; n < 12; n++) {
            unsigned Bv[2];
            const __half* bb = W2c + (8 * n + gid) * 16 + 2 * tig;
            Bv[0] = *(const unsigned*)(bb);
            Bv[1] = *(const unsigned*)(bb + 8);
#pragma unroll
            for (int i = 0; i < 2; i++) mma16(Y[i][n], pa[i], Bv);
        }
    }

    // ---- reduce Y across ds slices into fp32 smem [64][101] ----
    __syncthreads();
    float* Ys = (float*)smraw;   // aliases Hs + first weight buffers (dead)
#pragma unroll
    for (int d = 0; d < 4; d++) {
        if (ds == d) {
#pragma unroll
            for (int i = 0; i < 2; i++)
#pragma unroll
                for (int n = 0; n < 12; n++) {
                    int row = m0 + 16 * i + gid;
                    int col = 8 * n + 2 * tig;
                    if (d == 0) {
                        Ys[row * 101 + col]           = Y[i][n][0];
                        Ys[row * 101 + col + 1]       = Y[i][n][1];
                        Ys[(row + 8) * 101 + col]     = Y[i][n][2];
                        Ys[(row + 8) * 101 + col + 1] = Y[i][n][3];
                    } else {
                        Ys[row * 101 + col]           += Y[i][n][0];
                        Ys[row * 101 + col + 1]       += Y[i][n][1];
                        Ys[(row + 8) * 101 + col]     += Y[i][n][2];
                        Ys[(row + 8) * 101 + col + 1] += Y[i][n][3];
                    }
                }
        }
        __syncthreads();
    }

    // ---- residual + LN2 + LNf, one thread per token ----
    if (tid < 64) {
        int t = tid;
        const float* h1p = g_h1 + (size_t)b * CC * TT + t0 + t;
        float* yr = Ys + t * 101;
        float mu = 0.f;
#pragma unroll
        for (int c = 0; c < 96; c++) {
            float v = yr[c] + h1p[(size_t)c * TT] + B2F[c];
            yr[c] = v;
            mu += v;
        }
        mu *= (1.f / 96.f);
        float var = 0.f;
#pragma unroll
        for (int c = 0; c < 96; c++) {
            float d = yr[c] - mu;
            var += d * d;
        }
        var *= (1.f / 96.f);
        float rs1 = rsqrtf(var + EPSL);

        float m2 = 0.f, s2 = 0.f;
#pragma unroll
        for (int c = 0; c < 96; c++) {
            float z = (yr[c] - mu) * rs1 * G2S[c] + B2S[c];
            yr[c] = z;
            m2 += z;
            s2 += z * z;
        }
        m2 *= (1.f / 96.f);
        float var2 = s2 * (1.f / 96.f) - m2 * m2;
        float rs2 = rsqrtf(var2 + EPSL);

        float* ob = out + (size_t)b * CC * TT + t0 + t;
        for (int c = 0; c < 96; c++)
            ob[(size_t)c * TT] = (yr[c] - m2) * rs2 * GFS[c] + BFS[c];
    }
}

// =====================================================================
extern "C" void kernel_launch(void* const* d_in, const int* in_sizes, int n_in,
                              void* d_out, int out_size) {
    const float* x     = (const float*)d_in[0];
    const float* w_qkv = (const float*)d_in[1];
    const float* b_qkv = (const float*)d_in[2];
    const float* w_out = (const float*)d_in[3];
    const float* b_out = (const float*)d_in[4];
    const float* ln1_g = (const float*)d_in[5];
    const float* ln1_b = (const float*)d_in[6];
    const float* w_ff1 = (const float*)d_in[7];
    const float* b_ff1 = (const float*)d_in[8];
    const float* w_ff2 = (const float*)d_in[9];
    const float* b_ff2 = (const float*)d_in[10];
    const float* ln2_g = (const float*)d_in[11];
    const float* ln2_b = (const float*)d_in[12];
    const float* lnf_g = (const float*)d_in[13];
    const float* lnf_b = (const float*)d_in[14];
    float* out = (float*)d_out;

    const int smemQ  = (128 * XS2 + 288 * XS2) * 2;                                     // 86528
    const int smemAO = (64 * QSTR + 128 * QSTR + 32 * VSTR + 64 * XS2 + 96 * XS2) * 2;  // 57344
    const int smemF  = (64 * HSF + 4 * 2 * PBUF) * 2;                                   // 64512

    cudaFuncSetAttribute(k_qkv,        cudaFuncAttributeMaxDynamicSharedMemorySize, smemQ);
    cudaFuncSetAttribute(k_attn_oproj, cudaFuncAttributeMaxDynamicSharedMemorySize, smemAO);
    cudaFuncSetAttribute(k_ff,         cudaFuncAttributeMaxDynamicSharedMemorySize, smemF);

    k_prep<<<PREP_BLKS + 64 * 3 * BB, 256>>>(w_ff1, w_ff2, w_qkv, w_out, x);
    k_qkv<<<dim3(TT / 128, BB), 512, smemQ>>>(b_qkv);
    k_attn_oproj<<<dim3(TT / 64, BB), 128, smemAO>>>(x, b_out, ln1_g, ln1_b);
    k_ff<<<dim3(TT / 64, BB), 256, smemF>>>(b_ff1, b_ff2, ln2_g, ln2_b,
                                            lnf_g, lnf_b, out);
}

// round 14
// speedup vs baseline: 1.0212x; 1.0212x over previous
#include <cuda_runtime.h>
#include <cuda_fp16.h>
#include <stdint.h>
#include <math.h>

#define BB   8
#define TT   2048
#define CC   96
#define NH   3
#define HD   32
#define DFF  2048
#define HW   32
#define NKEY 65
#define EPSL 1e-5f

// ---- scratch (device globals; no allocation allowed) ----
__device__ float  g_h1 [(size_t)BB * CC * TT];      // post-LN1 (fp32, feature-major)
__device__ __half g_h16[(size_t)BB * TT * CC];      // post-LN1 (fp16, token-major)
__device__ __half g_w1h[(size_t)DFF * CC];          // fp16 W1
__device__ __half g_w2h[(size_t)CC * DFF];          // fp16 W2
__device__ __half g_wqh[(size_t)3 * CC * CC];       // fp16 W_qkv
__device__ __half g_woh[(size_t)CC * CC];           // fp16 W_out
__device__ __half g_x16[(size_t)BB * TT * CC];      // x, token-major fp16
__device__ __half g_qkv16[(size_t)BB * TT * 3 * CC];// qkv, token-major fp16

// =====================================================================
__device__ __forceinline__ void mma16(float* d, const unsigned* a, const unsigned* b) {
    asm("mma.sync.aligned.m16n8k16.row.col.f32.f16.f16.f32 "
        "{%0,%1,%2,%3}, {%4,%5,%6,%7}, {%8,%9}, {%0,%1,%2,%3};"
        : "+f"(d[0]), "+f"(d[1]), "+f"(d[2]), "+f"(d[3])
        : "r"(a[0]), "r"(a[1]), "r"(a[2]), "r"(a[3]), "r"(b[0]), "r"(b[1]));
}
// fp16-accumulate variant (double-rate on the fallback HMMA path)
__device__ __forceinline__ void mma16h(unsigned* d, const unsigned* a, const unsigned* b) {
    asm("mma.sync.aligned.m16n8k16.row.col.f16.f16.f16.f16 "
        "{%0,%1}, {%2,%3,%4,%5}, {%6,%7}, {%0,%1};"
        : "+r"(d[0]), "+r"(d[1])
        : "r"(a[0]), "r"(a[1]), "r"(a[2]), "r"(a[3]), "r"(b[0]), "r"(b[1]));
}
__device__ __forceinline__ void cpa16(void* dst, const void* src) {
    unsigned d = (unsigned)__cvta_generic_to_shared(dst);
    asm volatile("cp.async.cg.shared.global [%0], [%1], 16;" :: "r"(d), "l"(src));
}
__device__ __forceinline__ void cpa_commit() {
    asm volatile("cp.async.commit_group;" ::: "memory");
}
__device__ __forceinline__ void cpa_wait_all() {
    asm volatile("cp.async.wait_group 0;" ::: "memory");
}

// =====================================================================
// Kernel 0 (MERGED): weight prep + x transpose in one launch.
// =====================================================================
#define PREP_BLKS 768

__global__ __launch_bounds__(256) void k_prep(const float* __restrict__ w1,
                                              const float* __restrict__ w2,
                                              const float* __restrict__ wq,
                                              const float* __restrict__ wo,
                                              const float* __restrict__ x) {
    int bx = blockIdx.x;
    if (bx < PREP_BLKS) {
        int i = bx * 256 + threadIdx.x;
        if (i < DFF * CC) {
            g_w1h[i] = __float2half_rn(w1[i]);
            g_w2h[i] = __float2half_rn(w2[i]);
        }
        if (i < 3 * CC * CC) g_wqh[i] = __float2half_rn(wq[i]);
        if (i < CC * CC)     g_woh[i] = __float2half_rn(wo[i]);
        return;
    }
    __shared__ float tile[32][33];
    int bx2 = bx - PREP_BLKS;
    int tI = bx2 & 63;
    int rest = bx2 >> 6;
    int cI = rest % 3;
    int b  = rest / 3;
    int t0 = tI * 32;
    int c0 = cI * 32;
    int tx = threadIdx.x & 31, ty = threadIdx.x >> 5;

    const float* xb = x + (size_t)b * CC * TT;
#pragma unroll
    for (int i = 0; i < 4; i++)
        tile[ty + 8 * i][tx] = xb[(size_t)(c0 + ty + 8 * i) * TT + t0 + tx];
    __syncthreads();
    __half* ob = g_x16 + (size_t)b * TT * CC;
#pragma unroll
    for (int i = 0; i < 4; i++)
        ob[(size_t)(t0 + ty + 8 * i) * CC + c0 + tx] =
            __float2half_rn(tile[tx][ty + 8 * i]);
}

// =====================================================================
// Kernel 1: QKV via fp16 mma (unchanged, passing since R5)
// =====================================================================
#define XS2 104

__global__ __launch_bounds__(512, 1) void k_qkv(const float* __restrict__ bias) {
    extern __shared__ char smraw[];
    __half* Xs = (__half*)smraw;        // [128][104]
    __half* Wq = Xs + 128 * XS2;        // [288][104]

    int t0 = blockIdx.x * 128;
    int b  = blockIdx.y;
    int tid  = threadIdx.x;
    int lane = tid & 31;
    int w    = tid >> 5;
    int gid  = lane >> 2;
    int tig  = lane & 3;
    int m0 = (w & 3) * 32;
    int g0 = (w >> 2) * 72;

    const uint4* xsrc = (const uint4*)(g_x16 + ((size_t)b * TT + t0) * 96);
    for (int i = tid; i < 128 * 12; i += 512) {
        int tok = i / 12, seg = i - tok * 12;
        *(uint4*)(Xs + tok * XS2 + seg * 8) = xsrc[i];
    }
    const uint4* wsrc = (const uint4*)g_wqh;
    for (int i = tid; i < 288 * 12; i += 512) {
        int r = i / 12, q = i - r * 12;
        *(uint4*)(Wq + r * XS2 + q * 8) = wsrc[i];
    }
    __syncthreads();

    float acc[3][2][3][4];
#pragma unroll
    for (int jt = 0; jt < 3; jt++)
#pragma unroll
        for (int i = 0; i < 2; i++)
#pragma unroll
            for (int jj = 0; jj < 3; jj++)
#pragma unroll
                for (int r = 0; r < 4; r++) acc[jt][i][jj][r] = 0.f;

#pragma unroll
    for (int ks = 0; ks < 6; ks++) {
        int k0 = ks * 16;
        unsigned A[2][4];
#pragma unroll
        for (int i = 0; i < 2; i++) {
            const __half* base = Xs + (m0 + 16 * i + gid) * XS2 + k0 + 2 * tig;
            A[i][0] = *(const unsigned*)(base);
            A[i][1] = *(const unsigned*)(base + 8 * XS2);
            A[i][2] = *(const unsigned*)(base + 8);
            A[i][3] = *(const unsigned*)(base + 8 * XS2 + 8);
        }
#pragma unroll
        for (int jt = 0; jt < 3; jt++) {
            unsigned Bv[3][2];
#pragma unroll
            for (int jj = 0; jj < 3; jj++) {
                const __half* bb = Wq + (g0 + 24 * jt + 8 * jj + gid) * XS2 + k0 + 2 * tig;
                Bv[jj][0] = *(const unsigned*)(bb);
                Bv[jj][1] = *(const unsigned*)(bb + 8);
            }
#pragma unroll
            for (int i = 0; i < 2; i++)
#pragma unroll
                for (int jj = 0; jj < 3; jj++) mma16(acc[jt][i][jj], A[i], Bv[jj]);
        }
    }

    __half* ob = g_qkv16 + ((size_t)b * TT + t0) * 288;
#pragma unroll
    for (int jt = 0; jt < 3; jt++)
#pragma unroll
        for (int jj = 0; jj < 3; jj++) {
            int c = g0 + 24 * jt + 8 * jj + 2 * tig;
            float2 bv = *(const float2*)(bias + c);
#pragma unroll
            for (int i = 0; i < 2; i++) {
                int row = m0 + 16 * i + gid;
                __half2 lo = __floats2half2_rn(acc[jt][i][jj][0] + bv.x,
                                               acc[jt][i][jj][1] + bv.y);
                __half2 hi = __floats2half2_rn(acc[jt][i][jj][2] + bv.x,
                                               acc[jt][i][jj][3] + bv.y);
                *(__half2*)(ob + (size_t)row * 288 + c)       = lo;
                *(__half2*)(ob + (size_t)(row + 8) * 288 + c) = hi;
            }
        }
}

// =====================================================================
// Kernel 2 (FUSED): banded attention + out-proj + residual + LN1
// (unchanged, passing since R7)
// =====================================================================
#define QSTR 40
#define VSTR 136

__global__ __launch_bounds__(128, 1) void k_attn_oproj(const float* __restrict__ x,
                                                       const float* __restrict__ bo,
                                                       const float* __restrict__ g1,
                                                       const float* __restrict__ b1) {
    extern __shared__ char smraw[];
    __half* Qs  = (__half*)smraw;         // [64][40]
    __half* Ks  = Qs + 64 * QSTR;         // [128][40]
    __half* Vt  = Ks + 128 * QSTR;        // [32][136]
    __half* Ctx = Vt + 32 * VSTR;         // [64][104]
    __half* Wo  = Ctx + 64 * XS2;         // [96][104]
    __shared__ float BoS[96], G1S[96], B1S[96];

    int t0 = blockIdx.x * 64;
    int b  = blockIdx.y;
    int tid  = threadIdx.x;
    int lane = tid & 31;
    int w    = tid >> 5;
    int gid  = lane >> 2;
    int tig  = lane & 3;
    int m0a  = w * 16;
    int kbase = t0 - HW;

    const __half* qkvb = g_qkv16 + (size_t)b * TT * 288;

    const uint4* wsrc = (const uint4*)g_woh;
    for (int i = tid; i < 96 * 12; i += 128) {
        int r = i / 12, q = i - r * 12;
        *(uint4*)(Wo + r * XS2 + q * 8) = wsrc[i];
    }
    if (tid < 96) { BoS[tid] = bo[tid]; G1S[tid] = g1[tid]; B1S[tid] = b1[tid]; }

    for (int h = 0; h < NH; h++) {
        __syncthreads();

        for (int i = tid; i < 64 * 4; i += 128) {
            int r = i >> 2, seg = i & 3;
            *(uint4*)(Qs + r * QSTR + seg * 8) =
                *(const uint4*)(qkvb + (size_t)(t0 + r) * 288 + h * HD + seg * 8);
        }
        for (int i = tid; i < 128 * 4; i += 128) {
            int r = i >> 2, seg = i & 3;
            int s = kbase + r;
            uint4 v = make_uint4(0, 0, 0, 0);
            if (s >= 0 && s < TT)
                v = *(const uint4*)(qkvb + (size_t)s * 288 + 96 + h * HD + seg * 8);
            *(uint4*)(Ks + r * QSTR + seg * 8) = v;
        }
        {
            int r = tid;
            int s = kbase + r;
            uint4 vv[4];
            if (s >= 0 && s < TT) {
#pragma unroll
                for (int seg = 0; seg < 4; seg++)
                    vv[seg] = *(const uint4*)(qkvb + (size_t)s * 288 + 192 + h * HD + seg * 8);
            } else {
#pragma unroll
                for (int seg = 0; seg < 4; seg++) vv[seg] = make_uint4(0, 0, 0, 0);
            }
            const __half* vh = (const __half*)vv;
#pragma unroll
            for (int f = 0; f < 32; f++) Vt[f * VSTR + r] = vh[f];
        }
        __syncthreads();

        float s[16][4];
#pragma unroll
        for (int j = 0; j < 16; j++)
#pragma unroll
            for (int r = 0; r < 4; r++) s[j][r] = 0.f;

#pragma unroll
        for (int ks = 0; ks < 2; ks++) {
            int k0 = ks * 16;
            unsigned A[4];
            const __half* abase = Qs + (m0a + gid) * QSTR + k0 + 2 * tig;
            A[0] = *(const unsigned*)(abase);
            A[1] = *(const unsigned*)(abase + 8 * QSTR);
            A[2] = *(const unsigned*)(abase + 8);
            A[3] = *(const unsigned*)(abase + 8 * QSTR + 8);
#pragma unroll
            for (int j = 0; j < 16; j++) {
                unsigned Bv[2];
                const __half* bb = Ks + (8 * j + gid) * QSTR + k0 + 2 * tig;
                Bv[0] = *(const unsigned*)(bb);
                Bv[1] = *(const unsigned*)(bb + 8);
                mma16(s[j], A, Bv);
            }
        }

        const float scale = 0.17677669529663689f;
        int row0 = m0a + gid;
        int row1 = row0 + 8;
        float mx0 = -1e30f, mx1 = -1e30f;
#pragma unroll
        for (int j = 0; j < 16; j++) {
#pragma unroll
            for (int c = 0; c < 2; c++) {
                int col = 8 * j + 2 * tig + c;
                int key = kbase + col;
                bool in = (key >= 0) && (key < TT);
                bool v0 = in && (col >= row0) && (col <= row0 + 64);
                bool v1 = in && (col >= row1) && (col <= row1 + 64);
                s[j][c]     = v0 ? s[j][c] * scale     : -1e30f;
                s[j][c + 2] = v1 ? s[j][c + 2] * scale : -1e30f;
                mx0 = fmaxf(mx0, s[j][c]);
                mx1 = fmaxf(mx1, s[j][c + 2]);
            }
        }
        mx0 = fmaxf(mx0, __shfl_xor_sync(0xffffffffu, mx0, 1));
        mx0 = fmaxf(mx0, __shfl_xor_sync(0xffffffffu, mx0, 2));
        mx1 = fmaxf(mx1, __shfl_xor_sync(0xffffffffu, mx1, 1));
        mx1 = fmaxf(mx1, __shfl_xor_sync(0xffffffffu, mx1, 2));

        float sum0 = 0.f, sum1 = 0.f;
#pragma unroll
        for (int j = 0; j < 16; j++) {
            s[j][0] = __expf(s[j][0] - mx0);  sum0 += s[j][0];
            s[j][1] = __expf(s[j][1] - mx0);  sum0 += s[j][1];
            s[j][2] = __expf(s[j][2] - mx1);  sum1 += s[j][2];
            s[j][3] = __expf(s[j][3] - mx1);  sum1 += s[j][3];
        }
        sum0 += __shfl_xor_sync(0xffffffffu, sum0, 1);
        sum0 += __shfl_xor_sync(0xffffffffu, sum0, 2);
        sum1 += __shfl_xor_sync(0xffffffffu, sum1, 1);
        sum1 += __shfl_xor_sync(0xffffffffu, sum1, 2);
        float inv0 = 1.f / sum0, inv1 = 1.f / sum1;

        unsigned pa[8][4];
#pragma unroll
        for (int kt = 0; kt < 8; kt++) {
            __half2 a0 = __floats2half2_rn(s[2 * kt][0] * inv0,     s[2 * kt][1] * inv0);
            __half2 a1 = __floats2half2_rn(s[2 * kt][2] * inv1,     s[2 * kt][3] * inv1);
            __half2 a2 = __floats2half2_rn(s[2 * kt + 1][0] * inv0, s[2 * kt + 1][1] * inv0);
            __half2 a3 = __floats2half2_rn(s[2 * kt + 1][2] * inv1, s[2 * kt + 1][3] * inv1);
            pa[kt][0] = *reinterpret_cast<unsigned*>(&a0);
            pa[kt][1] = *reinterpret_cast<unsigned*>(&a1);
            pa[kt][2] = *reinterpret_cast<unsigned*>(&a2);
            pa[kt][3] = *reinterpret_cast<unsigned*>(&a3);
        }

        float o[4][4];
#pragma unroll
        for (int n = 0; n < 4; n++)
#pragma unroll
            for (int r = 0; r < 4; r++) o[n][r] = 0.f;

#pragma unroll
        for (int kt = 0; kt < 8; kt++) {
#pragma unroll
            for (int n = 0; n < 4; n++) {
                unsigned Bv[2];
                const __half* bb = Vt + (8 * n + gid) * VSTR + 16 * kt + 2 * tig;
                Bv[0] = *(const unsigned*)(bb);
                Bv[1] = *(const unsigned*)(bb + 8);
                mma16(o[n], pa[kt], Bv);
            }
        }

#pragma unroll
        for (int n = 0; n < 4; n++) {
            int col = h * HD + 8 * n + 2 * tig;
            __half2 lo = __floats2half2_rn(o[n][0], o[n][1]);
            __half2 hi = __floats2half2_rn(o[n][2], o[n][3]);
            *(__half2*)(Ctx + row0 * XS2 + col) = lo;
            *(__half2*)(Ctx + row1 * XS2 + col) = hi;
        }
    }
    __syncthreads();

    int m0 = (w & 1) * 32;
    int n0 = (w >> 1) * 48;
    float Y[2][6][4];
#pragma unroll
    for (int i = 0; i < 2; i++)
#pragma unroll
        for (int j = 0; j < 6; j++)
#pragma unroll
            for (int r = 0; r < 4; r++) Y[i][j][r] = 0.f;

#pragma unroll
    for (int ks = 0; ks < 6; ks++) {
        int k0 = ks * 16;
        unsigned A[2][4], Bv[6][2];
#pragma unroll
        for (int i = 0; i < 2; i++) {
            const __half* base = Ctx + (m0 + 16 * i + gid) * XS2 + k0 + 2 * tig;
            A[i][0] = *(const unsigned*)(base);
            A[i][1] = *(const unsigned*)(base + 8 * XS2);
            A[i][2] = *(const unsigned*)(base + 8);
            A[i][3] = *(const unsigned*)(base + 8 * XS2 + 8);
        }
#pragma unroll
        for (int j = 0; j < 6; j++) {
            const __half* bb = Wo + (n0 + 8 * j + gid) * XS2 + k0 + 2 * tig;
            Bv[j][0] = *(const unsigned*)(bb);
            Bv[j][1] = *(const unsigned*)(bb + 8);
        }
#pragma unroll
        for (int i = 0; i < 2; i++)
#pragma unroll
            for (int j = 0; j < 6; j++) mma16(Y[i][j], A[i], Bv[j]);
    }

    __syncthreads();
    float* Ys = (float*)smraw;   // [64][101]
#pragma unroll
    for (int i = 0; i < 2; i++)
#pragma unroll
        for (int j = 0; j < 6; j++) {
            int row = m0 + 16 * i + gid;
            int col = n0 + 8 * j + 2 * tig;
            Ys[row * 101 + col]           = Y[i][j][0];
            Ys[row * 101 + col + 1]       = Y[i][j][1];
            Ys[(row + 8) * 101 + col]     = Y[i][j][2];
            Ys[(row + 8) * 101 + col + 1] = Y[i][j][3];
        }
    __syncthreads();

    if (tid < 64) {
        int t = tid;
        const float* xb = x + (size_t)b * CC * TT + t0 + t;
        float* yr = Ys + t * 101;
        float mu = 0.f;
#pragma unroll
        for (int c = 0; c < 96; c++) {
            float v = yr[c] + xb[(size_t)c * TT] + BoS[c];
            yr[c] = v;
            mu += v;
        }
        mu *= (1.f / 96.f);
        float var = 0.f;
#pragma unroll
        for (int c = 0; c < 96; c++) {
            float d = yr[c] - mu;
            var += d * d;
        }
        var *= (1.f / 96.f);
        float rs = rsqrtf(var + EPSL);

        float* hb = g_h1 + (size_t)b * CC * TT + t0 + t;
        unsigned hu[48];
#pragma unroll
        for (int c = 0; c < 96; c += 2) {
            float v0 = (yr[c] - mu) * rs * G1S[c] + B1S[c];
            float v1 = (yr[c + 1] - mu) * rs * G1S[c + 1] + B1S[c + 1];
            hb[(size_t)c * TT] = v0;
            hb[(size_t)(c + 1) * TT] = v1;
            __half2 p = __floats2half2_rn(v0, v1);
            hu[c >> 1] = *reinterpret_cast<unsigned*>(&p);
        }
        uint4* dst = (uint4*)(g_h16 + ((size_t)b * TT + t0 + t) * 96);
#pragma unroll
        for (int qq = 0; qq < 12; qq++)
            dst[qq] = make_uint4(hu[4 * qq], hu[4 * qq + 1], hu[4 * qq + 2], hu[4 * qq + 3]);
    }
}

// =====================================================================
// Kernel 3: FF (R7 monolith structure) with fp16-accum u-phase.
// grid (T/128, B) = 128 blocks, 512 threads.
// =====================================================================
#define HS2 104
#define US2 72

__device__ __forceinline__ void stage_w(int jc, __half* W1d, __half* W2d, int tid) {
    const __half* w1h = g_w1h;
    const __half* w2h = g_w2h;
#pragma unroll
    for (int s = tid; s < 768; s += 512) {
        int r = s / 12, q = s - r * 12;
        cpa16(W1d + r * HS2 + q * 8, w1h + (size_t)(jc + r) * 96 + q * 8);
    }
#pragma unroll
    for (int s = tid; s < 768; s += 512) {
        int r = s >> 3, q = s & 7;
        cpa16(W2d + r * US2 + q * 8, w2h + (size_t)r * DFF + jc + q * 8);
    }
    cpa_commit();
}

__global__ __launch_bounds__(512, 1) void k_ff(const float* __restrict__ b1f,
                                               const float* __restrict__ b2f,
                                               const float* __restrict__ g2,
                                               const float* __restrict__ b2,
                                               const float* __restrict__ gf,
                                               const float* __restrict__ bf,
                                               float* __restrict__ out) {
    extern __shared__ char smraw[];
    __half* Hs  = (__half*)smraw;           // [128][104]
    __half* Us  = Hs + 128 * HS2;           // [128][72]
    __half* W1b = Us + 128 * US2;           // 2 x [64][104]
    __half* W2b = W1b + 2 * 64 * HS2;       // 2 x [96][72]
    __shared__ float B2F[96], G2S[96], B2S[96], GFS[96], BFS[96];

    int t0 = blockIdx.x * 128;
    int b  = blockIdx.y;
    int tid  = threadIdx.x;
    int lane = tid & 31;
    int w    = tid >> 5;
    int gid  = lane >> 2;
    int tig  = lane & 3;

    int m0u = (w & 3) * 32;
    int n0u = (w >> 2) * 16;
    int m0y = (w & 3) * 32;
    int n0y = (w >> 2) * 24;

    stage_w(0, W1b, W2b, tid);

    const uint4* hsrc = (const uint4*)(g_h16 + ((size_t)b * TT + t0) * 96);
    for (int i = tid; i < 128 * 12; i += 512) {
        int tok = i / 12, seg = i - tok * 12;
        *(uint4*)(Hs + tok * HS2 + seg * 8) = hsrc[i];
    }
    if (tid < 96) {
        B2F[tid] = b2f[tid]; G2S[tid] = g2[tid]; B2S[tid] = b2[tid];
        GFS[tid] = gf[tid];  BFS[tid] = bf[tid];
    }

    float Y[2][3][4];
#pragma unroll
    for (int i = 0; i < 2; i++)
#pragma unroll
        for (int j = 0; j < 3; j++)
#pragma unroll
            for (int r = 0; r < 4; r++) Y[i][j][r] = 0.f;

    for (int c = 0; c < 32; c++) {
        int jc = c * 64;
        __half* W1c = W1b + (c & 1) * 64 * HS2;
        __half* W2c = W2b + (c & 1) * 96 * US2;

        cpa_wait_all();
        __syncthreads();

        // ---- u-phase (fp16 accumulate): ua = Hs(tile) @ W1c(tile)^T ----
        unsigned ua[2][2][2];
#pragma unroll
        for (int i = 0; i < 2; i++)
#pragma unroll
            for (int j = 0; j < 2; j++) {
                ua[i][j][0] = 0u;
                ua[i][j][1] = 0u;
            }

#pragma unroll
        for (int ks = 0; ks < 6; ks++) {
            int k0 = ks * 16;
            unsigned A[2][4], Bv[2][2];
#pragma unroll
            for (int i = 0; i < 2; i++) {
                const __half* base = Hs + (m0u + 16 * i + gid) * HS2 + k0 + 2 * tig;
                A[i][0] = *(const unsigned*)(base);
                A[i][1] = *(const unsigned*)(base + 8 * HS2);
                A[i][2] = *(const unsigned*)(base + 8);
                A[i][3] = *(const unsigned*)(base + 8 * HS2 + 8);
            }
#pragma unroll
            for (int j = 0; j < 2; j++) {
                const __half* bb = W1c + (n0u + 8 * j + gid) * HS2 + k0 + 2 * tig;
                Bv[j][0] = *(const unsigned*)(bb);
                Bv[j][1] = *(const unsigned*)(bb + 8);
            }
#pragma unroll
            for (int i = 0; i < 2; i++)
#pragma unroll
                for (int j = 0; j < 2; j++) mma16h(ua[i][j], A[i], Bv[j]);
        }

        // bias + relu + store U  (D-frag: reg0 = rows gid, reg1 = rows gid+8)
#pragma unroll
        for (int j = 0; j < 2; j++) {
            float2 bv = *(const float2*)(b1f + jc + n0u + 8 * j + 2 * tig);
#pragma unroll
            for (int i = 0; i < 2; i++) {
                float2 vlo = __half22float2(*reinterpret_cast<__half2*>(&ua[i][j][0]));
                float2 vhi = __half22float2(*reinterpret_cast<__half2*>(&ua[i][j][1]));
                __half2 lo = __floats2half2_rn(fmaxf(vlo.x + bv.x, 0.f),
                                               fmaxf(vlo.y + bv.y, 0.f));
                __half2 hi = __floats2half2_rn(fmaxf(vhi.x + bv.x, 0.f),
                                               fmaxf(vhi.y + bv.y, 0.f));
                *(__half2*)(Us + (m0u + 16 * i + gid) * US2 + n0u + 8 * j + 2 * tig)     = lo;
                *(__half2*)(Us + (m0u + 16 * i + gid + 8) * US2 + n0u + 8 * j + 2 * tig) = hi;
            }
        }
        __syncthreads();

        if (c + 1 < 32)
            stage_w(jc + 64, W1b + ((c + 1) & 1) * 64 * HS2,
                    W2b + ((c + 1) & 1) * 96 * US2, tid);

        // ---- y-phase (fp32 accumulate): Y += Us(tile) @ W2c(tile)^T ----
#pragma unroll
        for (int ks = 0; ks < 4; ks++) {
            int k0 = ks * 16;
            unsigned A[2][4], Bv[3][2];
#pragma unroll
            for (int i = 0; i < 2; i++) {
                const __half* base = Us + (m0y + 16 * i + gid) * US2 + k0 + 2 * tig;
                A[i][0] = *(const unsigned*)(base);
                A[i][1] = *(const unsigned*)(base + 8 * US2);
                A[i][2] = *(const unsigned*)(base + 8);
                A[i][3] = *(const unsigned*)(base + 8 * US2 + 8);
            }
#pragma unroll
            for (int j = 0; j < 3; j++) {
                const __half* bb = W2c + (n0y + 8 * j + gid) * US2 + k0 + 2 * tig;
                Bv[j][0] = *(const unsigned*)(bb);
                Bv[j][1] = *(const unsigned*)(bb + 8);
            }
#pragma unroll
            for (int i = 0; i < 2; i++)
#pragma unroll
                for (int j = 0; j < 3; j++) mma16(Y[i][j], A[i], Bv[j]);
        }
    }

    __syncthreads();
    float* Ys = (float*)smraw;
#pragma unroll
    for (int i = 0; i < 2; i++)
#pragma unroll
        for (int j = 0; j < 3; j++) {
            int row = m0y + 16 * i + gid;
            int col = n0y + 8 * j + 2 * tig;
            Ys[row * 101 + col]           = Y[i][j][0];
            Ys[row * 101 + col + 1]       = Y[i][j][1];
            Ys[(row + 8) * 101 + col]     = Y[i][j][2];
            Ys[(row + 8) * 101 + col + 1] = Y[i][j][3];
        }
    __syncthreads();

    if (tid < 128) {
        int t = tid;
        const float* h1p = g_h1 + (size_t)b * CC * TT + t0 + t;
        float* yr = Ys + t * 101;
        float mu = 0.f;
#pragma unroll
        for (int c = 0; c < 96; c++) {
            float v = yr[c] + h1p[(size_t)c * TT] + B2F[c];
            yr[c] = v;
            mu += v;
        }
        mu *= (1.f / 96.f);
        float var = 0.f;
#pragma unroll
        for (int c = 0; c < 96; c++) {
            float d = yr[c] - mu;
            var += d * d;
        }
        var *= (1.f / 96.f);
        float rs1 = rsqrtf(var + EPSL);

        float m2 = 0.f, s2 = 0.f;
#pragma unroll
        for (int c = 0; c < 96; c++) {
            float z = (yr[c] - mu) * rs1 * G2S[c] + B2S[c];
            yr[c] = z;
            m2 += z;
            s2 += z * z;
        }
        m2 *= (1.f / 96.f);
        float var2 = s2 * (1.f / 96.f) - m2 * m2;
        float rs2 = rsqrtf(var2 + EPSL);

        float* ob = out + (size_t)b * CC * TT + t0 + t;
        for (int c = 0; c < 96; c++)
            ob[(size_t)c * TT] = (yr[c] - m2) * rs2 * GFS[c] + BFS[c];
    }
}

// =====================================================================
extern "C" void kernel_launch(void* const* d_in, const int* in_sizes, int n_in,
                              void* d_out, int out_size) {
    const float* x     = (const float*)d_in[0];
    const float* w_qkv = (const float*)d_in[1];
    const float* b_qkv = (const float*)d_in[2];
    const float* w_out = (const float*)d_in[3];
    const float* b_out = (const float*)d_in[4];
    const float* ln1_g = (const float*)d_in[5];
    const float* ln1_b = (const float*)d_in[6];
    const float* w_ff1 = (const float*)d_in[7];
    const float* b_ff1 = (const float*)d_in[8];
    const float* w_ff2 = (const float*)d_in[9];
    const float* b_ff2 = (const float*)d_in[10];
    const float* ln2_g = (const float*)d_in[11];
    const float* ln2_b = (const float*)d_in[12];
    const float* lnf_g = (const float*)d_in[13];
    const float* lnf_b = (const float*)d_in[14];
    float* out = (float*)d_out;

    const int smemQ  = (128 * XS2 + 288 * XS2) * 2;                                     // 86528
    const int smemAO = (64 * QSTR + 128 * QSTR + 32 * VSTR + 64 * XS2 + 96 * XS2) * 2;  // 57344
    const int smemF  = (128 * HS2 + 128 * US2 + 2 * 64 * HS2 + 2 * 96 * US2) * 2;       // 99328

    cudaFuncSetAttribute(k_qkv,        cudaFuncAttributeMaxDynamicSharedMemorySize, smemQ);
    cudaFuncSetAttribute(k_attn_oproj, cudaFuncAttributeMaxDynamicSharedMemorySize, smemAO);
    cudaFuncSetAttribute(k_ff,         cudaFuncAttributeMaxDynamicSharedMemorySize, smemF);

    k_prep<<<PREP_BLKS + 64 * 3 * BB, 256>>>(w_ff1, w_ff2, w_qkv, w_out, x);
    k_qkv<<<dim3(TT / 128, BB), 512, smemQ>>>(b_qkv);
    k_attn_oproj<<<dim3(TT / 64, BB), 128, smemAO>>>(x, b_out, ln1_g, ln1_b);
    k_ff<<<dim3(TT / 128, BB), 512, smemF>>>(b_ff1, b_ff2, ln2_g, ln2_b,
                                             lnf_g, lnf_b, out);
}